// round 8
// baseline (speedup 1.0000x reference)
#include <cuda_runtime.h>
#include <cuda_bf16.h>
#include <mma.h>
#include <cstdint>

#define N_NODES 100000
#define N_PAD   100096            // 782 * 128, lets tail CTA store unguarded
#define N_EDGES 1600000
#define D 128
#define SCAN_BLK 1024
#define N_SCAN_BLOCKS ((N_NODES + SCAN_BLK - 1) / SCAN_BLK)   // 98

using namespace nvcuda;

// Device scratch (allocation-rule-compliant __device__ globals)
__device__ float          g_support[(size_t)N_PAD * D];   // 51.2+ MB
__device__ int            g_count[N_NODES];
__device__ int            g_cursor[N_NODES];
__device__ int            g_rowstart[N_NODES + 1];
__device__ int            g_blocksum[N_SCAN_BLOCKS];
__device__ int            g_csr_col[N_EDGES];
__device__ float          g_csr_val[N_EDGES];
// B split images, [k][n] row-major bf16 (wmma matrix_b row_major layout)
__device__ __nv_bfloat16  g_Bhi[128 * 128];
__device__ __nv_bfloat16  g_Blo[128 * 128];

// ---------------------------------------------------------------------------
// Prep: split W into hi/lo bf16, stored [k][n] (B operand for A[m,k]*B[k,n]).
// ---------------------------------------------------------------------------
__global__ void prep_b_kernel(const float* __restrict__ W) {
    int idx = blockIdx.x * blockDim.x + threadIdx.x;
    if (idx >= 128 * 128) return;
    float x = W[idx];                       // W is already [k][n]
    __nv_bfloat16 hi = __float2bfloat16(x);
    __nv_bfloat16 lo = __float2bfloat16(x - __bfloat162float(hi));
    g_Bhi[idx] = hi;
    g_Blo[idx] = lo;
}

// ---------------------------------------------------------------------------
// Tensor-core GEMM via wmma (HMMA, family-generic PTX safe):
//   g_support[M,128] = A[M,128] @ W[128,128]
//   acc = Ahi*Bhi + Ahi*Blo + Alo*Bhi  (fp32 acc; lo*lo term ~2^-16, dropped)
// CTA: 128x128 tile, 256 threads = 8 warps, warp tile 32x64 (2x4 fragments).
// A (hi,lo) staged in SMEM (stride 136 -> conflict-light). B fragments are
// loaded directly from global (L1-resident 64KB, shared by all CTAs).
// 69.6 KB SMEM -> 2 CTAs/SM (vs 1 before): 2x memory parallelism.
// ---------------------------------------------------------------------------
#define A_STRIDE 136                         // 272B rows, 4-bank rotation
#define AHI_OFF 0
#define ALO_OFF (128 * A_STRIDE)
#define SM_BYTES (2 * 128 * A_STRIDE * 2)    // 69632

__global__ __launch_bounds__(256, 2) void gemm_wmma_kernel(const float* __restrict__ A) {
    extern __shared__ __nv_bfloat16 sm[];
    const int tid = threadIdx.x;
    const int wid = tid >> 5;
    const int blockM = blockIdx.x * 128;

    // --- Convert A tile fp32 -> (hi,lo) bf16 into SMEM. 16 float4/thread. ---
#pragma unroll 4
    for (int it = 0; it < 16; it++) {
        int linear = it * 256 + tid;         // 0..4095
        int row = linear >> 5;               // 0..127
        int kq = (linear & 31) << 2;         // 0,4,...,124
        int gr = blockM + row;
        float4 v = make_float4(0.f, 0.f, 0.f, 0.f);
        if (gr < N_NODES)
            v = *reinterpret_cast<const float4*>(A + (size_t)gr * D + kq);

        __nv_bfloat16 h0 = __float2bfloat16(v.x), h1 = __float2bfloat16(v.y);
        __nv_bfloat16 h2 = __float2bfloat16(v.z), h3 = __float2bfloat16(v.w);
        __nv_bfloat16 l0 = __float2bfloat16(v.x - __bfloat162float(h0));
        __nv_bfloat16 l1 = __float2bfloat16(v.y - __bfloat162float(h1));
        __nv_bfloat16 l2 = __float2bfloat16(v.z - __bfloat162float(h2));
        __nv_bfloat16 l3 = __float2bfloat16(v.w - __bfloat162float(h3));

        __nv_bfloat16* ah = sm + AHI_OFF + row * A_STRIDE + kq;
        __nv_bfloat16* al = sm + ALO_OFF + row * A_STRIDE + kq;
        *reinterpret_cast<__nv_bfloat162*>(ah)     = __nv_bfloat162(h0, h1);
        *reinterpret_cast<__nv_bfloat162*>(ah + 2) = __nv_bfloat162(h2, h3);
        *reinterpret_cast<__nv_bfloat162*>(al)     = __nv_bfloat162(l0, l1);
        *reinterpret_cast<__nv_bfloat162*>(al + 2) = __nv_bfloat162(l2, l3);
    }
    __syncthreads();

    // --- Warp-tiled MMA: wm = wid&3 (M 32-rows), wn = wid>>2 (N 64-cols) ---
    const int wm = (wid & 3) * 32;
    const int wn = (wid >> 2) * 64;

    wmma::fragment<wmma::accumulator, 16, 16, 16, float> acc[2][4];
#pragma unroll
    for (int i = 0; i < 2; i++)
#pragma unroll
        for (int j = 0; j < 4; j++) wmma::fill_fragment(acc[i][j], 0.0f);

#pragma unroll
    for (int sweep = 0; sweep < 3; sweep++) {
        const __nv_bfloat16* As = sm + ((sweep == 2) ? ALO_OFF : AHI_OFF);
        const __nv_bfloat16* Bg = (sweep == 1) ? g_Blo : g_Bhi;   // global/L1
#pragma unroll
        for (int k0 = 0; k0 < 128; k0 += 16) {
            wmma::fragment<wmma::matrix_a, 16, 16, 16, __nv_bfloat16, wmma::row_major> af[2];
#pragma unroll
            for (int i = 0; i < 2; i++)
                wmma::load_matrix_sync(af[i], As + (wm + i * 16) * A_STRIDE + k0, A_STRIDE);
#pragma unroll
            for (int j = 0; j < 4; j++) {
                wmma::fragment<wmma::matrix_b, 16, 16, 16, __nv_bfloat16, wmma::row_major> bf;
                wmma::load_matrix_sync(bf, Bg + k0 * 128 + wn + j * 16, 128);
#pragma unroll
                for (int i = 0; i < 2; i++)
                    wmma::mma_sync(acc[i][j], af[i], bf, acc[i][j]);
            }
        }
    }

    // --- Epilogue: direct store (g_support padded to N_PAD rows) ---
#pragma unroll
    for (int i = 0; i < 2; i++)
#pragma unroll
        for (int j = 0; j < 4; j++)
            wmma::store_matrix_sync(
                g_support + (size_t)(blockM + wm + i * 16) * D + wn + j * 16,
                acc[i][j], D, wmma::mem_row_major);
}

// ---------------------------------------------------------------------------
// CSR build
// ---------------------------------------------------------------------------
__global__ void zero_counts_kernel() {
    int i = blockIdx.x * blockDim.x + threadIdx.x;
    if (i < N_NODES) {
        g_count[i] = 0;
        g_cursor[i] = 0;
    }
}

// 4 edges per thread via int4
__global__ void hist_kernel(const int* __restrict__ edge_row) {
    int t = blockIdx.x * blockDim.x + threadIdx.x;
    int base = t * 4;
    if (base + 3 < N_EDGES) {
        int4 r = *reinterpret_cast<const int4*>(edge_row + base);
        atomicAdd(&g_count[r.x], 1);
        atomicAdd(&g_count[r.y], 1);
        atomicAdd(&g_count[r.z], 1);
        atomicAdd(&g_count[r.w], 1);
    } else {
        for (int e = base; e < N_EDGES; e++) atomicAdd(&g_count[edge_row[e]], 1);
    }
}

__global__ __launch_bounds__(SCAN_BLK) void scan_local_kernel() {
    __shared__ int warp_sums[32];
    const int tid = threadIdx.x;
    const int lane = tid & 31;
    const int wid = tid >> 5;
    const int i = blockIdx.x * SCAN_BLK + tid;

    int x = (i < N_NODES) ? g_count[i] : 0;
    int v = x;
#pragma unroll
    for (int o = 1; o < 32; o <<= 1) {
        int t = __shfl_up_sync(0xFFFFFFFFu, v, o);
        if (lane >= o) v += t;
    }
    if (lane == 31) warp_sums[wid] = v;
    __syncthreads();
    if (tid < 32) {
        int w = warp_sums[tid];
#pragma unroll
        for (int o = 1; o < 32; o <<= 1) {
            int t = __shfl_up_sync(0xFFFFFFFFu, w, o);
            if (tid >= o) w += t;
        }
        warp_sums[tid] = w;
    }
    __syncthreads();
    int incl = v + (wid > 0 ? warp_sums[wid - 1] : 0);
    if (i < N_NODES) g_rowstart[i] = incl - x;
    if (tid == SCAN_BLK - 1) g_blocksum[blockIdx.x] = incl;
}

__global__ __launch_bounds__(128) void scan_blocks_kernel() {
    __shared__ int warp_sums[4];
    const int tid = threadIdx.x;
    const int lane = tid & 31;
    const int wid = tid >> 5;
    int x = (tid < N_SCAN_BLOCKS) ? g_blocksum[tid] : 0;
    int v = x;
#pragma unroll
    for (int o = 1; o < 32; o <<= 1) {
        int t = __shfl_up_sync(0xFFFFFFFFu, v, o);
        if (lane >= o) v += t;
    }
    if (lane == 31) warp_sums[wid] = v;
    __syncthreads();
    if (tid < 4) {
        int w = warp_sums[tid];
#pragma unroll
        for (int o = 1; o < 4; o <<= 1) {
            int t = __shfl_up_sync(0xFu, w, o);
            if (tid >= o) w += t;
        }
        warp_sums[tid] = w;
    }
    __syncthreads();
    int incl = v + (wid > 0 ? warp_sums[wid - 1] : 0);
    if (tid < N_SCAN_BLOCKS) g_blocksum[tid] = incl - x;
    if (tid == N_SCAN_BLOCKS - 1) g_rowstart[N_NODES] = incl;
}

__global__ __launch_bounds__(SCAN_BLK) void scan_addoff_kernel() {
    const int i = blockIdx.x * SCAN_BLK + threadIdx.x;
    if (i < N_NODES) g_rowstart[i] += g_blocksum[blockIdx.x];
}

__global__ void fill_kernel(const float* __restrict__ edge_val,
                            const int* __restrict__ edge_row,
                            const int* __restrict__ edge_col) {
    int e = blockIdx.x * blockDim.x + threadIdx.x;
    if (e < N_EDGES) {
        int r = edge_row[e];
        int p = g_rowstart[r] + atomicAdd(&g_cursor[r], 1);
        g_csr_col[p] = edge_col[e];
        g_csr_val[p] = edge_val[e];
    }
}

// ---------------------------------------------------------------------------
// Gather: one warp per output row. acc = sum(val * support[col]); ReLU; store.
// ---------------------------------------------------------------------------
__global__ __launch_bounds__(256) void gather_kernel(float* __restrict__ out) {
    int row = blockIdx.x * 8 + (threadIdx.x >> 5);
    int lane = threadIdx.x & 31;
    if (row >= N_NODES) return;

    int s = g_rowstart[row];
    int e = g_rowstart[row + 1];

    float4 acc = make_float4(0.f, 0.f, 0.f, 0.f);
#pragma unroll 4
    for (int i = s; i < e; i++) {
        int c = g_csr_col[i];
        float v = g_csr_val[i];
        float4 sv = *reinterpret_cast<const float4*>(g_support + (size_t)c * D + lane * 4);
        acc.x = fmaf(v, sv.x, acc.x);
        acc.y = fmaf(v, sv.y, acc.y);
        acc.z = fmaf(v, sv.z, acc.z);
        acc.w = fmaf(v, sv.w, acc.w);
    }

    acc.x = fmaxf(acc.x, 0.f);
    acc.y = fmaxf(acc.y, 0.f);
    acc.z = fmaxf(acc.z, 0.f);
    acc.w = fmaxf(acc.w, 0.f);
    *reinterpret_cast<float4*>(out + (size_t)row * D + lane * 4) = acc;
}

extern "C" void kernel_launch(void* const* d_in, const int* in_sizes, int n_in,
                              void* d_out, int out_size) {
    const float* features = (const float*)d_in[0];   // [100000, 128]
    const float* weight   = (const float*)d_in[1];   // [128, 128]
    const float* edge_val = (const float*)d_in[2];   // [1600000]
    const int*   edge_row = (const int*)d_in[3];     // [1600000]
    const int*   edge_col = (const int*)d_in[4];     // [1600000]
    float* out = (float*)d_out;                      // [100000, 128]

    cudaFuncSetAttribute(gemm_wmma_kernel,
                         cudaFuncAttributeMaxDynamicSharedMemorySize, SM_BYTES);

    // 1) support = features @ W  (wmma split-bf16, B via L1)
    prep_b_kernel<<<64, 256>>>(weight);
    gemm_wmma_kernel<<<N_PAD / 128, 256, SM_BYTES>>>(features);

    // 2) CSR build with hierarchical scan
    zero_counts_kernel<<<(N_NODES + 255) / 256, 256>>>();
    hist_kernel<<<(N_EDGES / 4 + 255) / 256, 256>>>(edge_row);
    scan_local_kernel<<<N_SCAN_BLOCKS, SCAN_BLK>>>();
    scan_blocks_kernel<<<1, 128>>>();
    scan_addoff_kernel<<<N_SCAN_BLOCKS, SCAN_BLK>>>();
    fill_kernel<<<(N_EDGES + 255) / 256, 256>>>(edge_val, edge_row, edge_col);

    // 3) fused gather + ReLU -> out
    gather_kernel<<<(N_NODES + 7) / 8, 256>>>(out);
}

// round 10
// speedup vs baseline: 1.8626x; 1.8626x over previous
#include <cuda_runtime.h>
#include <cuda_bf16.h>
#include <mma.h>
#include <cstdint>

#define N_NODES 100000
#define N_PAD   100096            // 1564 * 64, lets tail CTA store unguarded
#define N_EDGES 1600000
#define D 128
#define SCAN_BLK 1024
#define N_SCAN_BLOCKS ((N_NODES + SCAN_BLK - 1) / SCAN_BLK)   // 98

using namespace nvcuda;

// Device scratch (allocation-rule-compliant __device__ globals)
__device__ float          g_support[(size_t)N_PAD * D];   // 51.2+ MB
__device__ int            g_count[N_NODES];
__device__ int            g_cursor[N_NODES];
__device__ int            g_rowstart[N_NODES + 1];
__device__ int            g_blocksum[N_SCAN_BLOCKS];
__device__ int            g_csr_col[N_EDGES];
__device__ float          g_csr_val[N_EDGES];
// B split images, [k][n] row-major bf16 (wmma matrix_b row_major layout)
__device__ __nv_bfloat16  g_Bhi[128 * 128];
__device__ __nv_bfloat16  g_Blo[128 * 128];

// ---------------------------------------------------------------------------
// Prep: split W into hi/lo bf16, stored [k][n] (B operand for A[m,k]*B[k,n]).
// ---------------------------------------------------------------------------
__global__ void prep_b_kernel(const float* __restrict__ W) {
    int idx = blockIdx.x * blockDim.x + threadIdx.x;
    if (idx >= 128 * 128) return;
    float x = W[idx];                       // W is already [k][n]
    __nv_bfloat16 hi = __float2bfloat16(x);
    __nv_bfloat16 lo = __float2bfloat16(x - __bfloat162float(hi));
    g_Bhi[idx] = hi;
    g_Blo[idx] = lo;
}

// ---------------------------------------------------------------------------
// Tensor-core GEMM via wmma (HMMA, family-generic PTX safe):
//   g_support[M,128] = A[M,128] @ W[128,128]
//   acc = Ahi*Bhi + Ahi*Blo + Alo*Bhi  (fp32 acc; lo*lo term ~2^-16, dropped)
// CTA: 64x128 tile, 256 threads = 8 warps, warp tile 32x32 (2x2 fragments).
// A (hi,lo) and B (hi,lo) staged in SMEM, both stride 136 (272B rows -> no
// bank aliasing). 104448 B SMEM -> 2 CTAs/SM.
// ---------------------------------------------------------------------------
#define STR 136
#define AHI_OFF 0
#define ALO_OFF (64 * STR)
#define BHI_OFF (128 * STR)
#define BLO_OFF (256 * STR)
#define SM_BYTES ((384 * STR) * 2)           // 104448

__global__ __launch_bounds__(256, 2) void gemm_wmma_kernel(const float* __restrict__ A) {
    extern __shared__ __nv_bfloat16 sm[];
    const int tid = threadIdx.x;
    const int wid = tid >> 5;
    const int blockM = blockIdx.x * 64;

    // --- Copy B splits into SMEM (stride 136). 8 uint4 per image/thread. ---
#pragma unroll
    for (int it = 0; it < 8; it++) {
        int v = it * 256 + tid;              // 0..2047
        int row = v >> 4;                    // 0..127
        int chunk = (v & 15) * 8;            // 0..120
        uint4 h = *reinterpret_cast<const uint4*>(g_Bhi + row * 128 + chunk);
        uint4 l = *reinterpret_cast<const uint4*>(g_Blo + row * 128 + chunk);
        *reinterpret_cast<uint4*>(sm + BHI_OFF + row * STR + chunk) = h;
        *reinterpret_cast<uint4*>(sm + BLO_OFF + row * STR + chunk) = l;
    }

    // --- Convert A tile fp32 -> (hi,lo) bf16 into SMEM. 8 float4/thread. ---
#pragma unroll
    for (int it = 0; it < 8; it++) {
        int linear = it * 256 + tid;         // 0..2047
        int row = linear >> 5;               // 0..63
        int kq = (linear & 31) << 2;         // 0,4,...,124
        int gr = blockM + row;
        float4 v = make_float4(0.f, 0.f, 0.f, 0.f);
        if (gr < N_NODES)
            v = *reinterpret_cast<const float4*>(A + (size_t)gr * D + kq);

        __nv_bfloat16 h0 = __float2bfloat16(v.x), h1 = __float2bfloat16(v.y);
        __nv_bfloat16 h2 = __float2bfloat16(v.z), h3 = __float2bfloat16(v.w);
        __nv_bfloat16 l0 = __float2bfloat16(v.x - __bfloat162float(h0));
        __nv_bfloat16 l1 = __float2bfloat16(v.y - __bfloat162float(h1));
        __nv_bfloat16 l2 = __float2bfloat16(v.z - __bfloat162float(h2));
        __nv_bfloat16 l3 = __float2bfloat16(v.w - __bfloat162float(h3));

        __nv_bfloat16* ah = sm + AHI_OFF + row * STR + kq;
        __nv_bfloat16* al = sm + ALO_OFF + row * STR + kq;
        *reinterpret_cast<__nv_bfloat162*>(ah)     = __nv_bfloat162(h0, h1);
        *reinterpret_cast<__nv_bfloat162*>(ah + 2) = __nv_bfloat162(h2, h3);
        *reinterpret_cast<__nv_bfloat162*>(al)     = __nv_bfloat162(l0, l1);
        *reinterpret_cast<__nv_bfloat162*>(al + 2) = __nv_bfloat162(l2, l3);
    }
    __syncthreads();

    // --- Warp-tiled MMA: wm = (wid&1)*32 (M), wn = (wid>>1)*32 (N) ---
    const int wm = (wid & 1) * 32;
    const int wn = (wid >> 1) * 32;

    wmma::fragment<wmma::accumulator, 16, 16, 16, float> acc[2][2];
#pragma unroll
    for (int i = 0; i < 2; i++)
#pragma unroll
        for (int j = 0; j < 2; j++) wmma::fill_fragment(acc[i][j], 0.0f);

#pragma unroll
    for (int sweep = 0; sweep < 3; sweep++) {
        const __nv_bfloat16* As = sm + ((sweep == 2) ? ALO_OFF : AHI_OFF);
        const __nv_bfloat16* Bs = sm + ((sweep == 1) ? BLO_OFF : BHI_OFF);
#pragma unroll
        for (int k0 = 0; k0 < 128; k0 += 16) {
            wmma::fragment<wmma::matrix_a, 16, 16, 16, __nv_bfloat16, wmma::row_major> af[2];
            wmma::fragment<wmma::matrix_b, 16, 16, 16, __nv_bfloat16, wmma::row_major> bf[2];
#pragma unroll
            for (int i = 0; i < 2; i++)
                wmma::load_matrix_sync(af[i], As + (wm + i * 16) * STR + k0, STR);
#pragma unroll
            for (int j = 0; j < 2; j++)
                wmma::load_matrix_sync(bf[j], Bs + k0 * STR + wn + j * 16, STR);
#pragma unroll
            for (int i = 0; i < 2; i++)
#pragma unroll
                for (int j = 0; j < 2; j++)
                    wmma::mma_sync(acc[i][j], af[i], bf[j], acc[i][j]);
        }
    }

    // --- Epilogue: direct store (g_support padded to N_PAD rows) ---
#pragma unroll
    for (int i = 0; i < 2; i++)
#pragma unroll
        for (int j = 0; j < 2; j++)
            wmma::store_matrix_sync(
                g_support + (size_t)(blockM + wm + i * 16) * D + wn + j * 16,
                acc[i][j], D, wmma::mem_row_major);
}

// ---------------------------------------------------------------------------
// CSR build
// ---------------------------------------------------------------------------
__global__ void zero_counts_kernel() {
    int i = blockIdx.x * blockDim.x + threadIdx.x;
    if (i < N_NODES) {
        g_count[i] = 0;
        g_cursor[i] = 0;
    }
}

// Simple 1-edge/thread version (measured faster than int4 batching)
__global__ void hist_kernel(const int* __restrict__ edge_row) {
    int e = blockIdx.x * blockDim.x + threadIdx.x;
    if (e < N_EDGES) atomicAdd(&g_count[edge_row[e]], 1);
}

__global__ __launch_bounds__(SCAN_BLK) void scan_local_kernel() {
    __shared__ int warp_sums[32];
    const int tid = threadIdx.x;
    const int lane = tid & 31;
    const int wid = tid >> 5;
    const int i = blockIdx.x * SCAN_BLK + tid;

    int x = (i < N_NODES) ? g_count[i] : 0;
    int v = x;
#pragma unroll
    for (int o = 1; o < 32; o <<= 1) {
        int t = __shfl_up_sync(0xFFFFFFFFu, v, o);
        if (lane >= o) v += t;
    }
    if (lane == 31) warp_sums[wid] = v;
    __syncthreads();
    if (tid < 32) {
        int w = warp_sums[tid];
#pragma unroll
        for (int o = 1; o < 32; o <<= 1) {
            int t = __shfl_up_sync(0xFFFFFFFFu, w, o);
            if (tid >= o) w += t;
        }
        warp_sums[tid] = w;
    }
    __syncthreads();
    int incl = v + (wid > 0 ? warp_sums[wid - 1] : 0);
    if (i < N_NODES) g_rowstart[i] = incl - x;
    if (tid == SCAN_BLK - 1) g_blocksum[blockIdx.x] = incl;
}

__global__ __launch_bounds__(128) void scan_blocks_kernel() {
    __shared__ int warp_sums[4];
    const int tid = threadIdx.x;
    const int lane = tid & 31;
    const int wid = tid >> 5;
    int x = (tid < N_SCAN_BLOCKS) ? g_blocksum[tid] : 0;
    int v = x;
#pragma unroll
    for (int o = 1; o < 32; o <<= 1) {
        int t = __shfl_up_sync(0xFFFFFFFFu, v, o);
        if (lane >= o) v += t;
    }
    if (lane == 31) warp_sums[wid] = v;
    __syncthreads();
    if (tid < 4) {
        int w = warp_sums[tid];
#pragma unroll
        for (int o = 1; o < 4; o <<= 1) {
            int t = __shfl_up_sync(0xFu, w, o);
            if (tid >= o) w += t;
        }
        warp_sums[tid] = w;
    }
    __syncthreads();
    int incl = v + (wid > 0 ? warp_sums[wid - 1] : 0);
    if (tid < N_SCAN_BLOCKS) g_blocksum[tid] = incl - x;
    if (tid == N_SCAN_BLOCKS - 1) g_rowstart[N_NODES] = incl;
}

__global__ __launch_bounds__(SCAN_BLK) void scan_addoff_kernel() {
    const int i = blockIdx.x * SCAN_BLK + threadIdx.x;
    if (i < N_NODES) g_rowstart[i] += g_blocksum[blockIdx.x];
}

__global__ void fill_kernel(const float* __restrict__ edge_val,
                            const int* __restrict__ edge_row,
                            const int* __restrict__ edge_col) {
    int e = blockIdx.x * blockDim.x + threadIdx.x;
    if (e < N_EDGES) {
        int r = edge_row[e];
        int p = g_rowstart[r] + atomicAdd(&g_cursor[r], 1);
        g_csr_col[p] = edge_col[e];
        g_csr_val[p] = edge_val[e];
    }
}

// ---------------------------------------------------------------------------
// Gather: one warp per output row. acc = sum(val * support[col]); ReLU; store.
// ---------------------------------------------------------------------------
__global__ __launch_bounds__(256) void gather_kernel(float* __restrict__ out) {
    int row = blockIdx.x * 8 + (threadIdx.x >> 5);
    int lane = threadIdx.x & 31;
    if (row >= N_NODES) return;

    int s = g_rowstart[row];
    int e = g_rowstart[row + 1];

    float4 acc = make_float4(0.f, 0.f, 0.f, 0.f);
#pragma unroll 4
    for (int i = s; i < e; i++) {
        int c = g_csr_col[i];
        float v = g_csr_val[i];
        float4 sv = *reinterpret_cast<const float4*>(g_support + (size_t)c * D + lane * 4);
        acc.x = fmaf(v, sv.x, acc.x);
        acc.y = fmaf(v, sv.y, acc.y);
        acc.z = fmaf(v, sv.z, acc.z);
        acc.w = fmaf(v, sv.w, acc.w);
    }

    acc.x = fmaxf(acc.x, 0.f);
    acc.y = fmaxf(acc.y, 0.f);
    acc.z = fmaxf(acc.z, 0.f);
    acc.w = fmaxf(acc.w, 0.f);
    *reinterpret_cast<float4*>(out + (size_t)row * D + lane * 4) = acc;
}

extern "C" void kernel_launch(void* const* d_in, const int* in_sizes, int n_in,
                              void* d_out, int out_size) {
    const float* features = (const float*)d_in[0];   // [100000, 128]
    const float* weight   = (const float*)d_in[1];   // [128, 128]
    const float* edge_val = (const float*)d_in[2];   // [1600000]
    const int*   edge_row = (const int*)d_in[3];     // [1600000]
    const int*   edge_col = (const int*)d_in[4];     // [1600000]
    float* out = (float*)d_out;                      // [100000, 128]

    cudaFuncSetAttribute(gemm_wmma_kernel,
                         cudaFuncAttributeMaxDynamicSharedMemorySize, SM_BYTES);

    // 1) support = features @ W  (wmma split-bf16, A+B in SMEM, 2 CTAs/SM)
    prep_b_kernel<<<64, 256>>>(weight);
    gemm_wmma_kernel<<<N_PAD / 64, 256, SM_BYTES>>>(features);

    // 2) CSR build with hierarchical scan
    zero_counts_kernel<<<(N_NODES + 255) / 256, 256>>>();
    hist_kernel<<<(N_EDGES + 255) / 256, 256>>>(edge_row);
    scan_local_kernel<<<N_SCAN_BLOCKS, SCAN_BLK>>>();
    scan_blocks_kernel<<<1, 128>>>();
    scan_addoff_kernel<<<N_SCAN_BLOCKS, SCAN_BLK>>>();
    fill_kernel<<<(N_EDGES + 255) / 256, 256>>>(edge_val, edge_row, edge_col);

    // 3) fused gather + ReLU -> out
    gather_kernel<<<(N_NODES + 7) / 8, 256>>>(out);
}

// round 12
// speedup vs baseline: 1.9111x; 1.0260x over previous
#include <cuda_runtime.h>
#include <cuda_bf16.h>
#include <mma.h>
#include <cstdint>

#define N_NODES 100000
#define N_PAD   100096            // 1564 * 64, lets tail CTA store unguarded
#define N_EDGES 1600000
#define D 128
#define SCAN_BLK 1024
#define N_SCAN_BLOCKS ((N_NODES + SCAN_BLK - 1) / SCAN_BLK)   // 98

using namespace nvcuda;

// Device scratch (allocation-rule-compliant __device__ globals)
__device__ float          g_support[(size_t)N_PAD * D];   // 51.2+ MB
__device__ int            g_count[N_NODES];
__device__ int            g_cursor[N_NODES];
__device__ int            g_rowstart[N_NODES + 1];
__device__ int            g_blocksum[N_SCAN_BLOCKS];
__device__ long long      g_csr_pair[N_EDGES];            // packed (val<<32 | col), 12.8 MB
// B split images, [k][n] row-major bf16 (wmma matrix_b row_major layout)
__device__ __nv_bfloat16  g_Bhi[128 * 128];
__device__ __nv_bfloat16  g_Blo[128 * 128];

// ---------------------------------------------------------------------------
// Prep: split W into hi/lo bf16 images AND zero count/cursor (merged kernels).
// ---------------------------------------------------------------------------
__global__ void prep_kernel(const float* __restrict__ W) {
    int idx = blockIdx.x * blockDim.x + threadIdx.x;
    if (idx < 128 * 128) {
        float x = W[idx];                   // W is already [k][n]
        __nv_bfloat16 hi = __float2bfloat16(x);
        __nv_bfloat16 lo = __float2bfloat16(x - __bfloat162float(hi));
        g_Bhi[idx] = hi;
        g_Blo[idx] = lo;
    }
    if (idx < N_NODES) {
        g_count[idx] = 0;
        g_cursor[idx] = 0;
    }
}

// ---------------------------------------------------------------------------
// Tensor-core GEMM via wmma (HMMA, family-generic PTX safe):
//   g_support[M,128] = A[M,128] @ W[128,128]
//   acc = Ahi*Bhi + Ahi*Blo + Alo*Bhi  (fp32 acc; lo*lo term ~2^-16, dropped)
// CTA: 64x128 tile, 256 threads = 8 warps, warp tile 32x32 (2x2 fragments).
// A (hi,lo) and B (hi,lo) in SMEM, stride 136 (272B rows -> no bank aliasing).
// Epilogue stages the fp32 result in SMEM (reusing the A region) and emits
// coalesced float4 global stores instead of scattered STG.32.
// 104448 B SMEM -> 2 CTAs/SM.
// ---------------------------------------------------------------------------
#define STR 136
#define AHI_OFF 0
#define ALO_OFF (64 * STR)
#define BHI_OFF (128 * STR)
#define BLO_OFF (256 * STR)
#define SM_BYTES ((384 * STR) * 2)           // 104448
// Epilogue fp32 staging reuses bytes [0, 34816) = A hi+lo region.
// 64 rows x stride 136 floats (544 B, 16B multiple) = 34816 B exactly.
#define EPI_STRF 136

__global__ __launch_bounds__(256, 2) void gemm_wmma_kernel(const float* __restrict__ A) {
    extern __shared__ __nv_bfloat16 sm[];
    float* smf = reinterpret_cast<float*>(sm);   // epilogue view (same bytes)
    const int tid = threadIdx.x;
    const int wid = tid >> 5;
    const int blockM = blockIdx.x * 64;

    // --- Copy B splits into SMEM (stride 136). 8 uint4 per image/thread. ---
#pragma unroll
    for (int it = 0; it < 8; it++) {
        int v = it * 256 + tid;              // 0..2047
        int row = v >> 4;                    // 0..127
        int chunk = (v & 15) * 8;            // 0..120
        uint4 h = *reinterpret_cast<const uint4*>(g_Bhi + row * 128 + chunk);
        uint4 l = *reinterpret_cast<const uint4*>(g_Blo + row * 128 + chunk);
        *reinterpret_cast<uint4*>(sm + BHI_OFF + row * STR + chunk) = h;
        *reinterpret_cast<uint4*>(sm + BLO_OFF + row * STR + chunk) = l;
    }

    // --- Convert A tile fp32 -> (hi,lo) bf16 into SMEM. 8 float4/thread. ---
#pragma unroll
    for (int it = 0; it < 8; it++) {
        int linear = it * 256 + tid;         // 0..2047
        int row = linear >> 5;               // 0..63
        int kq = (linear & 31) << 2;         // 0,4,...,124
        int gr = blockM + row;
        float4 v = make_float4(0.f, 0.f, 0.f, 0.f);
        if (gr < N_NODES)
            v = *reinterpret_cast<const float4*>(A + (size_t)gr * D + kq);

        __nv_bfloat16 h0 = __float2bfloat16(v.x), h1 = __float2bfloat16(v.y);
        __nv_bfloat16 h2 = __float2bfloat16(v.z), h3 = __float2bfloat16(v.w);
        __nv_bfloat16 l0 = __float2bfloat16(v.x - __bfloat162float(h0));
        __nv_bfloat16 l1 = __float2bfloat16(v.y - __bfloat162float(h1));
        __nv_bfloat16 l2 = __float2bfloat16(v.z - __bfloat162float(h2));
        __nv_bfloat16 l3 = __float2bfloat16(v.w - __bfloat162float(h3));

        __nv_bfloat16* ah = sm + AHI_OFF + row * STR + kq;
        __nv_bfloat16* al = sm + ALO_OFF + row * STR + kq;
        *reinterpret_cast<__nv_bfloat162*>(ah)     = __nv_bfloat162(h0, h1);
        *reinterpret_cast<__nv_bfloat162*>(ah + 2) = __nv_bfloat162(h2, h3);
        *reinterpret_cast<__nv_bfloat162*>(al)     = __nv_bfloat162(l0, l1);
        *reinterpret_cast<__nv_bfloat162*>(al + 2) = __nv_bfloat162(l2, l3);
    }
    __syncthreads();

    // --- Warp-tiled MMA: wm = (wid&1)*32 (M), wn = (wid>>1)*32 (N) ---
    const int wm = (wid & 1) * 32;
    const int wn = (wid >> 1) * 32;

    wmma::fragment<wmma::accumulator, 16, 16, 16, float> acc[2][2];
#pragma unroll
    for (int i = 0; i < 2; i++)
#pragma unroll
        for (int j = 0; j < 2; j++) wmma::fill_fragment(acc[i][j], 0.0f);

#pragma unroll
    for (int sweep = 0; sweep < 3; sweep++) {
        const __nv_bfloat16* As = sm + ((sweep == 2) ? ALO_OFF : AHI_OFF);
        const __nv_bfloat16* Bs = sm + ((sweep == 1) ? BLO_OFF : BHI_OFF);
#pragma unroll
        for (int k0 = 0; k0 < 128; k0 += 16) {
            wmma::fragment<wmma::matrix_a, 16, 16, 16, __nv_bfloat16, wmma::row_major> af[2];
            wmma::fragment<wmma::matrix_b, 16, 16, 16, __nv_bfloat16, wmma::row_major> bf[2];
#pragma unroll
            for (int i = 0; i < 2; i++)
                wmma::load_matrix_sync(af[i], As + (wm + i * 16) * STR + k0, STR);
#pragma unroll
            for (int j = 0; j < 2; j++)
                wmma::load_matrix_sync(bf[j], Bs + k0 * STR + wn + j * 16, STR);
#pragma unroll
            for (int i = 0; i < 2; i++)
#pragma unroll
                for (int j = 0; j < 2; j++)
                    wmma::mma_sync(acc[i][j], af[i], bf[j], acc[i][j]);
        }
    }

    // --- Epilogue: stage in SMEM (A region is dead now), then coalesced STG ---
    __syncthreads();     // all warps done reading A region
#pragma unroll
    for (int i = 0; i < 2; i++)
#pragma unroll
        for (int j = 0; j < 2; j++)
            wmma::store_matrix_sync(smf + (wm + i * 16) * EPI_STRF + wn + j * 16,
                                    acc[i][j], EPI_STRF, wmma::mem_row_major);
    __syncthreads();

    // 64 rows x 128 floats = 2048 float4; 8 per thread, coalesced.
#pragma unroll
    for (int it = 0; it < 8; it++) {
        int v = it * 256 + tid;              // 0..2047
        int row = v >> 5;                    // 0..63
        int q = (v & 31) << 2;               // 0,4,...,124
        float4 w = *reinterpret_cast<const float4*>(smf + row * EPI_STRF + q);
        *reinterpret_cast<float4*>(g_support + (size_t)(blockM + row) * D + q) = w;
    }
}

// ---------------------------------------------------------------------------
// CSR build
// ---------------------------------------------------------------------------
__global__ void hist_kernel(const int* __restrict__ edge_row) {
    int e = blockIdx.x * blockDim.x + threadIdx.x;
    if (e < N_EDGES) atomicAdd(&g_count[edge_row[e]], 1);
}

__global__ __launch_bounds__(SCAN_BLK) void scan_local_kernel() {
    __shared__ int warp_sums[32];
    const int tid = threadIdx.x;
    const int lane = tid & 31;
    const int wid = tid >> 5;
    const int i = blockIdx.x * SCAN_BLK + tid;

    int x = (i < N_NODES) ? g_count[i] : 0;
    int v = x;
#pragma unroll
    for (int o = 1; o < 32; o <<= 1) {
        int t = __shfl_up_sync(0xFFFFFFFFu, v, o);
        if (lane >= o) v += t;
    }
    if (lane == 31) warp_sums[wid] = v;
    __syncthreads();
    if (tid < 32) {
        int w = warp_sums[tid];
#pragma unroll
        for (int o = 1; o < 32; o <<= 1) {
            int t = __shfl_up_sync(0xFFFFFFFFu, w, o);
            if (tid >= o) w += t;
        }
        warp_sums[tid] = w;
    }
    __syncthreads();
    int incl = v + (wid > 0 ? warp_sums[wid - 1] : 0);
    if (i < N_NODES) g_rowstart[i] = incl - x;
    if (tid == SCAN_BLK - 1) g_blocksum[blockIdx.x] = incl;
}

__global__ __launch_bounds__(128) void scan_blocks_kernel() {
    __shared__ int warp_sums[4];
    const int tid = threadIdx.x;
    const int lane = tid & 31;
    const int wid = tid >> 5;
    int x = (tid < N_SCAN_BLOCKS) ? g_blocksum[tid] : 0;
    int v = x;
#pragma unroll
    for (int o = 1; o < 32; o <<= 1) {
        int t = __shfl_up_sync(0xFFFFFFFFu, v, o);
        if (lane >= o) v += t;
    }
    if (lane == 31) warp_sums[wid] = v;
    __syncthreads();
    if (tid < 4) {
        int w = warp_sums[tid];
#pragma unroll
        for (int o = 1; o < 4; o <<= 1) {
            int t = __shfl_up_sync(0xFu, w, o);
            if (tid >= o) w += t;
        }
        warp_sums[tid] = w;
    }
    __syncthreads();
    int incl = v + (wid > 0 ? warp_sums[wid - 1] : 0);
    if (tid < N_SCAN_BLOCKS) g_blocksum[tid] = incl - x;
    if (tid == N_SCAN_BLOCKS - 1) g_rowstart[N_NODES] = incl;
}

__global__ __launch_bounds__(SCAN_BLK) void scan_addoff_kernel() {
    const int i = blockIdx.x * SCAN_BLK + threadIdx.x;
    if (i < N_NODES) g_rowstart[i] += g_blocksum[blockIdx.x];
}

// Fill CSR as packed 8-byte (val,col) pairs: one scattered STG.64 per edge.
__global__ void fill_kernel(const float* __restrict__ edge_val,
                            const int* __restrict__ edge_row,
                            const int* __restrict__ edge_col) {
    int e = blockIdx.x * blockDim.x + threadIdx.x;
    if (e < N_EDGES) {
        int r = edge_row[e];
        int p = g_rowstart[r] + atomicAdd(&g_cursor[r], 1);
        long long pair = ((long long)(unsigned int)__float_as_uint(edge_val[e]) << 32)
                       | (unsigned int)edge_col[e];
        g_csr_pair[p] = pair;
    }
}

// ---------------------------------------------------------------------------
// Gather: one warp per output row. acc = sum(val * support[col]); ReLU; store.
// One LDG.64 per edge for (val,col).
// ---------------------------------------------------------------------------
__global__ __launch_bounds__(256) void gather_kernel(float* __restrict__ out) {
    int row = blockIdx.x * 8 + (threadIdx.x >> 5);
    int lane = threadIdx.x & 31;
    if (row >= N_NODES) return;

    int s = g_rowstart[row];
    int e = g_rowstart[row + 1];

    float4 acc = make_float4(0.f, 0.f, 0.f, 0.f);
#pragma unroll 4
    for (int i = s; i < e; i++) {
        long long pair = g_csr_pair[i];
        int c = (int)(unsigned int)(pair & 0xffffffffLL);
        float v = __uint_as_float((unsigned int)((unsigned long long)pair >> 32));
        float4 sv = *reinterpret_cast<const float4*>(g_support + (size_t)c * D + lane * 4);
        acc.x = fmaf(v, sv.x, acc.x);
        acc.y = fmaf(v, sv.y, acc.y);
        acc.z = fmaf(v, sv.z, acc.z);
        acc.w = fmaf(v, sv.w, acc.w);
    }

    acc.x = fmaxf(acc.x, 0.f);
    acc.y = fmaxf(acc.y, 0.f);
    acc.z = fmaxf(acc.z, 0.f);
    acc.w = fmaxf(acc.w, 0.f);
    *reinterpret_cast<float4*>(out + (size_t)row * D + lane * 4) = acc;
}

extern "C" void kernel_launch(void* const* d_in, const int* in_sizes, int n_in,
                              void* d_out, int out_size) {
    const float* features = (const float*)d_in[0];   // [100000, 128]
    const float* weight   = (const float*)d_in[1];   // [128, 128]
    const float* edge_val = (const float*)d_in[2];   // [1600000]
    const int*   edge_row = (const int*)d_in[3];     // [1600000]
    const int*   edge_col = (const int*)d_in[4];     // [1600000]
    float* out = (float*)d_out;                      // [100000, 128]

    cudaFuncSetAttribute(gemm_wmma_kernel,
                         cudaFuncAttributeMaxDynamicSharedMemorySize, SM_BYTES);

    // 1) prep (B split + counter zeroing) then GEMM
    prep_kernel<<<(N_NODES + 255) / 256, 256>>>(weight);
    gemm_wmma_kernel<<<N_PAD / 64, 256, SM_BYTES>>>(features);

    // 2) CSR build with hierarchical scan
    hist_kernel<<<(N_EDGES + 255) / 256, 256>>>(edge_row);
    scan_local_kernel<<<N_SCAN_BLOCKS, SCAN_BLK>>>();
    scan_blocks_kernel<<<1, 128>>>();
    scan_addoff_kernel<<<N_SCAN_BLOCKS, SCAN_BLK>>>();
    fill_kernel<<<(N_EDGES + 255) / 256, 256>>>(edge_val, edge_row, edge_col);

    // 3) fused gather + ReLU -> out
    gather_kernel<<<(N_NODES + 7) / 8, 256>>>(out);
}

// round 13
// speedup vs baseline: 1.9819x; 1.0370x over previous
#include <cuda_runtime.h>
#include <cuda_bf16.h>
#include <mma.h>
#include <cstdint>

#define N_NODES 100000
#define N_PAD   100096            // 1564 * 64, lets tail tile store unguarded
#define N_TILES (N_PAD / 64)      // 1564
#define N_EDGES 1600000
#define D 128
#define GEMM_GRID 296             // 2 CTAs/SM * 148 SMs (persistent)
#define SCAN_BLK 1024
#define N_SCAN_BLOCKS ((N_NODES + SCAN_BLK - 1) / SCAN_BLK)   // 98

using namespace nvcuda;

// Device scratch (allocation-rule-compliant __device__ globals)
__device__ float          g_support[(size_t)N_PAD * D];   // 51.2+ MB
__device__ int            g_count[N_NODES];
__device__ int            g_cursor[N_NODES];
__device__ int            g_rowstart[N_NODES + 1];
__device__ int            g_blocksum[N_SCAN_BLOCKS];
__device__ long long      g_csr_pair[N_EDGES];            // packed (val<<32 | col)
// B split images, [k][n] row-major bf16 (wmma matrix_b row_major layout)
__device__ __nv_bfloat16  g_Bhi[128 * 128];
__device__ __nv_bfloat16  g_Blo[128 * 128];

// ---------------------------------------------------------------------------
// Prep: split W into hi/lo bf16 images AND zero count/cursor (merged kernels).
// ---------------------------------------------------------------------------
__global__ void prep_kernel(const float* __restrict__ W) {
    int idx = blockIdx.x * blockDim.x + threadIdx.x;
    if (idx < 128 * 128) {
        float x = W[idx];                   // W is already [k][n]
        __nv_bfloat16 hi = __float2bfloat16(x);
        __nv_bfloat16 lo = __float2bfloat16(x - __bfloat162float(hi));
        g_Bhi[idx] = hi;
        g_Blo[idx] = lo;
    }
    if (idx < N_NODES) {
        g_count[idx] = 0;
        g_cursor[idx] = 0;
    }
}

// ---------------------------------------------------------------------------
// Persistent fused kernel:
//  Phase A: tensor-core GEMM g_support = A @ W (split-bf16, 3 sweeps).
//    B loaded to SMEM ONCE per CTA (not once per tile): B L2 traffic
//    100 MB -> 19 MB. Each CTA loops tiles with stride gridDim.x.
//  Phase B: histogram of edge_row (independent of GEMM; runs in the
//    straggler slack as CTAs finish their tile loops).
// CTA: 256 threads = 8 warps, M-tile 64, warp tile 32x32 (2x2 fragments).
// SMEM 104448 B -> 2 CTAs/SM.
// ---------------------------------------------------------------------------
#define STR 136
#define AHI_OFF 0
#define ALO_OFF (64 * STR)
#define BHI_OFF (128 * STR)
#define BLO_OFF (256 * STR)
#define SM_BYTES ((384 * STR) * 2)           // 104448
#define EPI_STRF 136                         // epilogue fp32 staging (A region)

__global__ __launch_bounds__(256, 2) void gemm_hist_kernel(const float* __restrict__ A,
                                                           const int* __restrict__ edge_row) {
    extern __shared__ __nv_bfloat16 sm[];
    float* smf = reinterpret_cast<float*>(sm);   // epilogue view (same bytes)
    const int tid = threadIdx.x;
    const int wid = tid >> 5;

    // --- Load B splits into SMEM ONCE. 8 uint4 per image/thread. ---
#pragma unroll
    for (int it = 0; it < 8; it++) {
        int v = it * 256 + tid;              // 0..2047
        int row = v >> 4;                    // 0..127
        int chunk = (v & 15) * 8;            // 0..120
        uint4 h = *reinterpret_cast<const uint4*>(g_Bhi + row * 128 + chunk);
        uint4 l = *reinterpret_cast<const uint4*>(g_Blo + row * 128 + chunk);
        *reinterpret_cast<uint4*>(sm + BHI_OFF + row * STR + chunk) = h;
        *reinterpret_cast<uint4*>(sm + BLO_OFF + row * STR + chunk) = l;
    }

    const int wm = (wid & 1) * 32;
    const int wn = (wid >> 1) * 32;

    for (int tile = blockIdx.x; tile < N_TILES; tile += gridDim.x) {
        const int blockM = tile * 64;

        __syncthreads();   // prior iter's epilogue SMEM reads done; B copy visible (1st iter)

        // --- Convert A tile fp32 -> (hi,lo) bf16 into SMEM. 8 float4/thread. ---
#pragma unroll
        for (int it = 0; it < 8; it++) {
            int linear = it * 256 + tid;     // 0..2047
            int row = linear >> 5;           // 0..63
            int kq = (linear & 31) << 2;     // 0,4,...,124
            int gr = blockM + row;
            float4 v = make_float4(0.f, 0.f, 0.f, 0.f);
            if (gr < N_NODES)
                v = *reinterpret_cast<const float4*>(A + (size_t)gr * D + kq);

            __nv_bfloat16 h0 = __float2bfloat16(v.x), h1 = __float2bfloat16(v.y);
            __nv_bfloat16 h2 = __float2bfloat16(v.z), h3 = __float2bfloat16(v.w);
            __nv_bfloat16 l0 = __float2bfloat16(v.x - __bfloat162float(h0));
            __nv_bfloat16 l1 = __float2bfloat16(v.y - __bfloat162float(h1));
            __nv_bfloat16 l2 = __float2bfloat16(v.z - __bfloat162float(h2));
            __nv_bfloat16 l3 = __float2bfloat16(v.w - __bfloat162float(h3));

            __nv_bfloat16* ah = sm + AHI_OFF + row * STR + kq;
            __nv_bfloat16* al = sm + ALO_OFF + row * STR + kq;
            *reinterpret_cast<__nv_bfloat162*>(ah)     = __nv_bfloat162(h0, h1);
            *reinterpret_cast<__nv_bfloat162*>(ah + 2) = __nv_bfloat162(h2, h3);
            *reinterpret_cast<__nv_bfloat162*>(al)     = __nv_bfloat162(l0, l1);
            *reinterpret_cast<__nv_bfloat162*>(al + 2) = __nv_bfloat162(l2, l3);
        }
        __syncthreads();

        // --- Warp-tiled MMA, 3 precision sweeps ---
        wmma::fragment<wmma::accumulator, 16, 16, 16, float> acc[2][2];
#pragma unroll
        for (int i = 0; i < 2; i++)
#pragma unroll
            for (int j = 0; j < 2; j++) wmma::fill_fragment(acc[i][j], 0.0f);

#pragma unroll
        for (int sweep = 0; sweep < 3; sweep++) {
            const __nv_bfloat16* As = sm + ((sweep == 2) ? ALO_OFF : AHI_OFF);
            const __nv_bfloat16* Bs = sm + ((sweep == 1) ? BLO_OFF : BHI_OFF);
#pragma unroll
            for (int k0 = 0; k0 < 128; k0 += 16) {
                wmma::fragment<wmma::matrix_a, 16, 16, 16, __nv_bfloat16, wmma::row_major> af[2];
                wmma::fragment<wmma::matrix_b, 16, 16, 16, __nv_bfloat16, wmma::row_major> bf[2];
#pragma unroll
                for (int i = 0; i < 2; i++)
                    wmma::load_matrix_sync(af[i], As + (wm + i * 16) * STR + k0, STR);
#pragma unroll
                for (int j = 0; j < 2; j++)
                    wmma::load_matrix_sync(bf[j], Bs + k0 * STR + wn + j * 16, STR);
#pragma unroll
                for (int i = 0; i < 2; i++)
#pragma unroll
                    for (int j = 0; j < 2; j++)
                        wmma::mma_sync(acc[i][j], af[i], bf[j], acc[i][j]);
            }
        }

        // --- Epilogue: stage fp32 in SMEM (A region dead), coalesced STG ---
        __syncthreads();     // all warps done reading A region
#pragma unroll
        for (int i = 0; i < 2; i++)
#pragma unroll
            for (int j = 0; j < 2; j++)
                wmma::store_matrix_sync(smf + (wm + i * 16) * EPI_STRF + wn + j * 16,
                                        acc[i][j], EPI_STRF, wmma::mem_row_major);
        __syncthreads();

#pragma unroll
        for (int it = 0; it < 8; it++) {
            int v = it * 256 + tid;          // 0..2047
            int row = v >> 5;                // 0..63
            int q = (v & 31) << 2;           // 0,4,...,124
            float4 w = *reinterpret_cast<const float4*>(smf + row * EPI_STRF + q);
            *reinterpret_cast<float4*>(g_support + (size_t)(tile * 64 + row) * D + q) = w;
        }
    }

    // --- Phase B: histogram (independent of GEMM output) ---
    for (int e = blockIdx.x * 256 + tid; e < N_EDGES; e += gridDim.x * 256)
        atomicAdd(&g_count[edge_row[e]], 1);
}

// ---------------------------------------------------------------------------
// Hierarchical exclusive scan of g_count -> g_rowstart
// ---------------------------------------------------------------------------
__global__ __launch_bounds__(SCAN_BLK) void scan_local_kernel() {
    __shared__ int warp_sums[32];
    const int tid = threadIdx.x;
    const int lane = tid & 31;
    const int wid = tid >> 5;
    const int i = blockIdx.x * SCAN_BLK + tid;

    int x = (i < N_NODES) ? g_count[i] : 0;
    int v = x;
#pragma unroll
    for (int o = 1; o < 32; o <<= 1) {
        int t = __shfl_up_sync(0xFFFFFFFFu, v, o);
        if (lane >= o) v += t;
    }
    if (lane == 31) warp_sums[wid] = v;
    __syncthreads();
    if (tid < 32) {
        int w = warp_sums[tid];
#pragma unroll
        for (int o = 1; o < 32; o <<= 1) {
            int t = __shfl_up_sync(0xFFFFFFFFu, w, o);
            if (tid >= o) w += t;
        }
        warp_sums[tid] = w;
    }
    __syncthreads();
    int incl = v + (wid > 0 ? warp_sums[wid - 1] : 0);
    if (i < N_NODES) g_rowstart[i] = incl - x;
    if (tid == SCAN_BLK - 1) g_blocksum[blockIdx.x] = incl;
}

__global__ __launch_bounds__(128) void scan_blocks_kernel() {
    __shared__ int warp_sums[4];
    const int tid = threadIdx.x;
    const int lane = tid & 31;
    const int wid = tid >> 5;
    int x = (tid < N_SCAN_BLOCKS) ? g_blocksum[tid] : 0;
    int v = x;
#pragma unroll
    for (int o = 1; o < 32; o <<= 1) {
        int t = __shfl_up_sync(0xFFFFFFFFu, v, o);
        if (lane >= o) v += t;
    }
    if (lane == 31) warp_sums[wid] = v;
    __syncthreads();
    if (tid < 4) {
        int w = warp_sums[tid];
#pragma unroll
        for (int o = 1; o < 4; o <<= 1) {
            int t = __shfl_up_sync(0xFu, w, o);
            if (tid >= o) w += t;
        }
        warp_sums[tid] = w;
    }
    __syncthreads();
    int incl = v + (wid > 0 ? warp_sums[wid - 1] : 0);
    if (tid < N_SCAN_BLOCKS) g_blocksum[tid] = incl - x;
    if (tid == N_SCAN_BLOCKS - 1) g_rowstart[N_NODES] = incl;
}

__global__ __launch_bounds__(SCAN_BLK) void scan_addoff_kernel() {
    const int i = blockIdx.x * SCAN_BLK + threadIdx.x;
    if (i < N_NODES) g_rowstart[i] += g_blocksum[blockIdx.x];
}

// Fill CSR as packed 8-byte (val,col) pairs: one scattered STG.64 per edge.
__global__ void fill_kernel(const float* __restrict__ edge_val,
                            const int* __restrict__ edge_row,
                            const int* __restrict__ edge_col) {
    int e = blockIdx.x * blockDim.x + threadIdx.x;
    if (e < N_EDGES) {
        int r = edge_row[e];
        int p = g_rowstart[r] + atomicAdd(&g_cursor[r], 1);
        long long pair = ((long long)(unsigned int)__float_as_uint(edge_val[e]) << 32)
                       | (unsigned int)edge_col[e];
        g_csr_pair[p] = pair;
    }
}

// ---------------------------------------------------------------------------
// Gather: one warp per output row. acc = sum(val * support[col]); ReLU; store.
// ---------------------------------------------------------------------------
__global__ __launch_bounds__(256) void gather_kernel(float* __restrict__ out) {
    int row = blockIdx.x * 8 + (threadIdx.x >> 5);
    int lane = threadIdx.x & 31;
    if (row >= N_NODES) return;

    int s = g_rowstart[row];
    int e = g_rowstart[row + 1];

    float4 acc = make_float4(0.f, 0.f, 0.f, 0.f);
#pragma unroll 4
    for (int i = s; i < e; i++) {
        long long pair = g_csr_pair[i];
        int c = (int)(unsigned int)(pair & 0xffffffffLL);
        float v = __uint_as_float((unsigned int)((unsigned long long)pair >> 32));
        float4 sv = *reinterpret_cast<const float4*>(g_support + (size_t)c * D + lane * 4);
        acc.x = fmaf(v, sv.x, acc.x);
        acc.y = fmaf(v, sv.y, acc.y);
        acc.z = fmaf(v, sv.z, acc.z);
        acc.w = fmaf(v, sv.w, acc.w);
    }

    acc.x = fmaxf(acc.x, 0.f);
    acc.y = fmaxf(acc.y, 0.f);
    acc.z = fmaxf(acc.z, 0.f);
    acc.w = fmaxf(acc.w, 0.f);
    *reinterpret_cast<float4*>(out + (size_t)row * D + lane * 4) = acc;
}

extern "C" void kernel_launch(void* const* d_in, const int* in_sizes, int n_in,
                              void* d_out, int out_size) {
    const float* features = (const float*)d_in[0];   // [100000, 128]
    const float* weight   = (const float*)d_in[1];   // [128, 128]
    const float* edge_val = (const float*)d_in[2];   // [1600000]
    const int*   edge_row = (const int*)d_in[3];     // [1600000]
    const int*   edge_col = (const int*)d_in[4];     // [1600000]
    float* out = (float*)d_out;                      // [100000, 128]

    cudaFuncSetAttribute(gemm_hist_kernel,
                         cudaFuncAttributeMaxDynamicSharedMemorySize, SM_BYTES);

    // 1) prep (B split + counter zeroing)
    prep_kernel<<<(N_NODES + 255) / 256, 256>>>(weight);

    // 2) persistent fused GEMM + histogram
    gemm_hist_kernel<<<GEMM_GRID, 256, SM_BYTES>>>(features, edge_row);

    // 3) scan + fill
    scan_local_kernel<<<N_SCAN_BLOCKS, SCAN_BLK>>>();
    scan_blocks_kernel<<<1, 128>>>();
    scan_addoff_kernel<<<N_SCAN_BLOCKS, SCAN_BLK>>>();
    fill_kernel<<<(N_EDGES + 255) / 256, 256>>>(edge_val, edge_row, edge_col);

    // 4) fused gather + ReLU -> out
    gather_kernel<<<(N_NODES + 7) / 8, 256>>>(out);
}